// round 10
// baseline (speedup 1.0000x reference)
#include <cuda_runtime.h>
#include <math.h>

#define NN 512
#define SS 64
#define CC 1024
#define BB 10
#define SB 4                        // s-positions per CTA
#define CHUNKS (SS / SB)            // 16 CTAs per row
#define PI_ELEMS (NN * SS * CC)
#define TILE_BYTES (SB * CC * 4)    // 16 KB per CTA

__device__ __forceinline__ unsigned smem_u32(const void* p) {
    unsigned a;
    asm("{ .reg .u64 t; cvta.to.shared.u64 t, %1; cvt.u32.u64 %0, t; }"
        : "=r"(a) : "l"(p));
    return a;
}

// ---------------------------------------------------------------------------
// Single fused kernel. 8192 CTAs x 256 threads, no global scratch.
// Per CTA:
//   hist (64 smem atomics) -> Z via O(1) atomicExch dedupe (<=64 expf)
//   -> SB lse -> mask-folded compute into smem tile -> ONE cp.async.bulk.
// ---------------------------------------------------------------------------
__global__ __launch_bounds__(256) void spop_kernel(
    const int* __restrict__ ban_ids,
    const int* __restrict__ item_ids,
    float* __restrict__ out)
{
    __shared__ alignas(128) float s_tile[SB * CC];       // 16 KB
    __shared__ int      s_hist[CC];                      // 4 KB
    __shared__ int      s_flag[CC / 4];                  // claim bitmap-ish (u8 via int)
    __shared__ int      s_ids[SS];
    __shared__ int      s_ban[SB * BB];
    __shared__ unsigned s_mask[SB][CC / 32];
    __shared__ float    s_l[SB];
    __shared__ int      s_last;
    __shared__ float    s_Z;

    const int blk   = blockIdx.x;
    const int n     = blk >> 4;               // CHUNKS == 16
    const int chunk = blk & 15;
    const int s0    = chunk * SB;
    const int tid   = threadIdx.x;
    const int lane  = tid & 31;
    const int c0    = tid * 4;

    // ---- init + loads, all independent ----
    reinterpret_cast<int4*>(s_hist)[tid] = make_int4(0, 0, 0, 0);
    if (tid < CC / 4) s_flag[tid] = 0;        // one int = 4 packed u8 flags
    if (tid < SS) s_ids[tid] = item_ids[n * SS + tid];
    int myban = 0;
    if (tid < SB * BB) {
        myban = ban_ids[(n * SS + s0) * BB + tid];
        s_ban[tid] = myban;
    }
    if (tid >= 128 && tid < 128 + SB * (CC / 32))
        (&s_mask[0][0])[tid - 128] = 0u;
    if (tid == 0) { s_last = -1; s_Z = 1024.0f; }
    if (chunk == 0 && tid < SS) out[PI_ELEMS + n * SS + tid] = 0.0f;  // v zeros
    __syncthreads();

    // ---- last non-pad (PAD == 0) + ban bitmask ----
    if (tid < SS && s_ids[tid] != 0) atomicMax(&s_last, tid);
    if (tid < SB * BB)
        atomicOr(&s_mask[tid / BB][myban >> 5], 1u << (myban & 31));
    __syncthreads();

    // ---- histogram, dropping the last non-pad element ----
    const bool counted = (tid < SS) && (s_ids[tid] != 0) && (tid != s_last);
    const int  myid    = counted ? s_ids[tid] : 0;
    if (counted) atomicAdd(&s_hist[myid], 1);
    __syncthreads();

    // ---- Z = 1024 + sum over DISTINCT counted ids of (e^h - 1) ----
    // O(1) dedupe: claim the id's byte flag; first claimant computes expf.
    {
        float zp = 0.0f;
        if (counted) {
            const int old = atomicOr(&s_flag[myid >> 2], 1 << ((myid & 3) * 8));
            if (((old >> ((myid & 3) * 8)) & 0xff) == 0)
                zp = expf((float)s_hist[myid]) - 1.0f;
        }
        if (tid < SS) {                       // warps 0-1 hold all nonzero zp
            #pragma unroll
            for (int off = 16; off; off >>= 1)
                zp += __shfl_xor_sync(0xffffffffu, zp, off);
            if (lane == 0) atomicAdd(&s_Z, zp);
        }
    }
    __syncthreads();

    // ---- per-s lse with rank-10 distinct-banned correction ----
    if (tid < SB) {
        float corr = 0.0f;
        int ids[BB];
        #pragma unroll
        for (int j = 0; j < BB; ++j) {
            const int id = s_ban[tid * BB + j];
            ids[j] = id;
            bool dup = false;
            #pragma unroll
            for (int k = 0; k < BB; ++k) if (k < j) dup |= (ids[k] == id);
            if (!dup) corr += expf((float)s_hist[id]);
        }
        s_l[tid] = logf(fmaxf(s_Z - corr, 1e-35f));
    }
    __syncthreads();

    // ---- compute tile in smem (mask folded), then ONE bulk store ----
    const int4 h = reinterpret_cast<const int4*>(s_hist)[tid];
    const float f0 = (float)h.x, f1 = (float)h.y;
    const float f2 = (float)h.z, f3 = (float)h.w;

    float4* __restrict__ tile4 = reinterpret_cast<float4*>(s_tile);
    #pragma unroll
    for (int s = 0; s < SB; ++s) {
        const float    l = s_l[s];
        const unsigned m = s_mask[s][c0 >> 5] >> (c0 & 31);
        float4 o;
        o.x = f0 - l - ((m & 1u) ? 1e9f : 0.0f);
        o.y = f1 - l - ((m & 2u) ? 1e9f : 0.0f);
        o.z = f2 - l - ((m & 4u) ? 1e9f : 0.0f);
        o.w = f3 - l - ((m & 8u) ? 1e9f : 0.0f);
        tile4[s * (CC / 4) + tid] = o;        // STS.128, conflict-free
    }
    __syncthreads();                          // tile complete

    if (tid == 0) {
        float* dst = out + (n * SS + s0) * CC;
        const unsigned src = smem_u32(s_tile);
        asm volatile("fence.proxy.async.shared::cta;" ::: "memory");
        asm volatile(
            "cp.async.bulk.global.shared::cta.bulk_group [%0], [%1], %2;"
            :: "l"(dst), "r"(src), "r"((int)TILE_BYTES) : "memory");
        asm volatile("cp.async.bulk.commit_group;" ::: "memory");
        asm volatile("cp.async.bulk.wait_group 0;" ::: "memory");
    }
}

extern "C" void kernel_launch(void* const* d_in, const int* in_sizes, int n_in,
                              void* d_out, int out_size) {
    // metadata order: null_w (f32, unused), ban_ids (i32 [N,S,B]), item_ids (i32 [N,S])
    const int* ban_ids  = (const int*)d_in[1];
    const int* item_ids = (const int*)d_in[2];
    float* out = (float*)d_out;

    spop_kernel<<<NN * CHUNKS, 256>>>(ban_ids, item_ids, out);
}